// round 1
// baseline (speedup 1.0000x reference)
#include <cuda_runtime.h>
#include <math.h>

#define NN   20000      // nodes
#define NE   256000     // edges per path
#define MP   3          // metapaths
#define INS  256        // in feature size
#define NH   8          // heads
#define FH   64         // out per head
#define DD   512        // NH*FH
#define HID  128
#define NEG_SLOPE 0.2f
#define RROWS (NN*MP)

// ---------------- scratch (device globals; no cudaMalloc allowed) ----------------
__device__ float g_feat[(size_t)MP * NN * DD];   // [m][n][d]
__device__ float g_z[(size_t)NN * MP * DD];      // [n][m][d]
__device__ float g_el[MP * NN * NH];
__device__ float g_er[MP * NN * NH];
__device__ int   g_rowptr[MP][NN + 1];
__device__ int   g_cnt[MP][NN];
__device__ int   g_colidx[MP][NE];
__device__ int   g_part[MP][64];
__device__ float g_wsum[MP];
__device__ float g_beta[MP];

// ---------------- init: zero histogram + semantic accumulators ----------------
__global__ void init_kernel() {
    int i = blockIdx.x * 256 + threadIdx.x;
    if (i < MP * NN) ((int*)g_cnt)[i] = 0;
    if (i < MP) g_wsum[i] = 0.0f;
}

// ---------------- GEMM1: feat[m] = h @ W[m]   (128x128x8 tile, TM=TN=8) ----------------
__global__ __launch_bounds__(256) void gemm_feat_kernel(const float* __restrict__ hmat,
                                                        const float* __restrict__ Wmat) {
    int m = blockIdx.z;
    const float* B = Wmat + (size_t)m * INS * DD;
    float* C = g_feat + (size_t)m * NN * DD;

    __shared__ float As[8][128];
    __shared__ float Bs[8][128];

    int tid = threadIdx.x;
    int row0 = blockIdx.y * 128;
    int col0 = blockIdx.x * 128;

    int arow = tid >> 1;            // 0..127
    int acol = (tid & 1) * 4;       // 0 or 4
    int brow = tid >> 5;            // 0..7
    int bcol = (tid & 31) * 4;

    int ty = tid >> 4, tx = tid & 15;

    float acc[8][8];
#pragma unroll
    for (int i = 0; i < 8; i++)
#pragma unroll
        for (int j = 0; j < 8; j++) acc[i][j] = 0.0f;

    for (int k0 = 0; k0 < INS; k0 += 8) {
        float4 av = make_float4(0.f, 0.f, 0.f, 0.f);
        int ar = row0 + arow;
        if (ar < NN) av = *(const float4*)(hmat + (size_t)ar * INS + k0 + acol);
        As[acol + 0][arow] = av.x;
        As[acol + 1][arow] = av.y;
        As[acol + 2][arow] = av.z;
        As[acol + 3][arow] = av.w;
        *(float4*)&Bs[brow][bcol] = *(const float4*)(B + (size_t)(k0 + brow) * DD + col0 + bcol);
        __syncthreads();
#pragma unroll
        for (int k = 0; k < 8; k++) {
            float4 a0 = *(const float4*)&As[k][ty * 8];
            float4 a1 = *(const float4*)&As[k][ty * 8 + 4];
            float4 b0 = *(const float4*)&Bs[k][tx * 8];
            float4 b1 = *(const float4*)&Bs[k][tx * 8 + 4];
            float ra[8] = {a0.x, a0.y, a0.z, a0.w, a1.x, a1.y, a1.z, a1.w};
            float rb[8] = {b0.x, b0.y, b0.z, b0.w, b1.x, b1.y, b1.z, b1.w};
#pragma unroll
            for (int i = 0; i < 8; i++)
#pragma unroll
                for (int j = 0; j < 8; j++) acc[i][j] += ra[i] * rb[j];
        }
        __syncthreads();
    }
#pragma unroll
    for (int i = 0; i < 8; i++) {
        int r = row0 + ty * 8 + i;
        if (r < NN) {
            float4 v0 = make_float4(acc[i][0], acc[i][1], acc[i][2], acc[i][3]);
            float4 v1 = make_float4(acc[i][4], acc[i][5], acc[i][6], acc[i][7]);
            *(float4*)(C + (size_t)r * DD + col0 + tx * 8)     = v0;
            *(float4*)(C + (size_t)r * DD + col0 + tx * 8 + 4) = v1;
        }
    }
}

// ---------------- el/er: per (path,node) head dot products; one warp each ----------------
__global__ void el_er_kernel(const float* __restrict__ attn_l, const float* __restrict__ attn_r) {
    int gw = blockIdx.x * 8 + (threadIdx.x >> 5);
    if (gw >= MP * NN) return;
    int m = gw / NN, n = gw % NN;
    int lane = threadIdx.x & 31;
    const float* frow = g_feat + ((size_t)m * NN + n) * DD;

    float pl[8], pr[8];
#pragma unroll
    for (int h = 0; h < 8; h++) { pl[h] = 0.f; pr[h] = 0.f; }
#pragma unroll
    for (int j = 0; j < 16; j++) {
        int c = lane + 32 * j;
        int hh = j >> 1;
        int fi = lane + 32 * (j & 1);
        float f = frow[c];
        pl[hh] += f * attn_l[(m * NH + hh) * FH + fi];
        pr[hh] += f * attn_r[(m * NH + hh) * FH + fi];
    }
#pragma unroll
    for (int off = 16; off > 0; off >>= 1) {
#pragma unroll
        for (int h = 0; h < 8; h++) {
            pl[h] += __shfl_xor_sync(0xffffffffu, pl[h], off);
            pr[h] += __shfl_xor_sync(0xffffffffu, pr[h], off);
        }
    }
    if (lane < 8) {
        g_el[((size_t)m * NN + n) * NH + lane] = pl[lane];
        g_er[((size_t)m * NN + n) * NH + lane] = pr[lane];
    }
}

// ---------------- CSR build ----------------
__global__ void hist_kernel(const int* __restrict__ dst) {
    int i = blockIdx.x * 256 + threadIdx.x;
    if (i >= MP * NE) return;
    int m = i / NE;
    atomicAdd(&g_cnt[m][dst[i]], 1);
}

__global__ void scanA_kernel() {
    int m = blockIdx.y;
    int c0 = blockIdx.x * 1024;
    int tid = threadIdx.x;
    __shared__ int s[256];
    int v[4]; int sum = 0;
#pragma unroll
    for (int t = 0; t < 4; t++) {
        int i = c0 + tid * 4 + t;
        v[t] = (i < NN) ? g_cnt[m][i] : 0;
        sum += v[t];
    }
    s[tid] = sum;
    __syncthreads();
    for (int off = 1; off < 256; off <<= 1) {
        int t = (tid >= off) ? s[tid - off] : 0;
        __syncthreads();
        s[tid] += t;
        __syncthreads();
    }
    int run = s[tid] - sum;   // exclusive prefix for this thread
#pragma unroll
    for (int t = 0; t < 4; t++) {
        int i = c0 + tid * 4 + t;
        if (i < NN) g_rowptr[m][i] = run;
        run += v[t];
    }
    if (tid == 255) g_part[m][blockIdx.x] = s[255];
}

__global__ void scanB_kernel() {
    int m = blockIdx.x;
    if (threadIdx.x == 0) {
        int run = 0;
        const int nchunk = (NN + 1023) / 1024;
        for (int c = 0; c < nchunk; c++) { int t = g_part[m][c]; g_part[m][c] = run; run += t; }
    }
}

__global__ void scanC_kernel() {
    int m = blockIdx.y;
    int i = blockIdx.x * 256 + threadIdx.x;
    if (i < NN) {
        g_rowptr[m][i] += g_part[m][i >> 10];
        g_cnt[m][i] = 0;   // becomes the scatter cursor
    }
    if (i == 0) g_rowptr[m][NN] = NE;
}

__global__ void scatter_kernel(const int* __restrict__ dst) {
    int i = blockIdx.x * 256 + threadIdx.x;
    if (i >= MP * NE) return;
    int m = i / NE, e = i % NE;
    int d = dst[i];
    int pos = g_rowptr[m][d] + atomicAdd(&g_cnt[m][d], 1);
    g_colidx[m][pos] = e;
}

// ---------------- gather: per-dst softmax + weighted aggregation. One warp per (n,m). ----------------
__global__ __launch_bounds__(256) void gather_kernel(const int* __restrict__ src,
                                                     const float* __restrict__ bias,
                                                     float* __restrict__ out_alpha) {
    int m = blockIdx.y;
    int n = blockIdx.x * 8 + (threadIdx.x >> 5);
    if (n >= NN) return;
    int lane = threadIdx.x & 31;

    int beg = g_rowptr[m][n];
    int end = g_rowptr[m][n + 1];

    const float* el = g_el + (size_t)m * NN * NH;
    float er8[8];
    {
        const float4* e4 = (const float4*)(g_er + ((size_t)m * NN + n) * NH);
        float4 a = e4[0], b = e4[1];
        er8[0] = a.x; er8[1] = a.y; er8[2] = a.z; er8[3] = a.w;
        er8[4] = b.x; er8[5] = b.y; er8[6] = b.z; er8[7] = b.w;
    }

    float4 acc[4];
#pragma unroll
    for (int j = 0; j < 4; j++) acc[j] = make_float4(0.f, 0.f, 0.f, 0.f);

    if (end > beg) {
        float mx[8];
#pragma unroll
        for (int h = 0; h < 8; h++) mx[h] = -INFINITY;
        // pass 1: max per head
        for (int idx = beg + lane; idx < end; idx += 32) {
            int e = g_colidx[m][idx];
            int s = src[(size_t)m * NE + e];
            const float4* s4 = (const float4*)(el + (size_t)s * NH);
            float4 a = s4[0], b = s4[1];
            float ev[8] = {a.x, a.y, a.z, a.w, b.x, b.y, b.z, b.w};
#pragma unroll
            for (int h = 0; h < 8; h++) {
                float x = ev[h] + er8[h];
                x = (x > 0.f) ? x : NEG_SLOPE * x;
                mx[h] = fmaxf(mx[h], x);
            }
        }
#pragma unroll
        for (int off = 16; off > 0; off >>= 1)
#pragma unroll
            for (int h = 0; h < 8; h++) mx[h] = fmaxf(mx[h], __shfl_xor_sync(0xffffffffu, mx[h], off));

        // pass 2: sum of exp
        float sm[8];
#pragma unroll
        for (int h = 0; h < 8; h++) sm[h] = 0.f;
        for (int idx = beg + lane; idx < end; idx += 32) {
            int e = g_colidx[m][idx];
            int s = src[(size_t)m * NE + e];
            const float4* s4 = (const float4*)(el + (size_t)s * NH);
            float4 a = s4[0], b = s4[1];
            float ev[8] = {a.x, a.y, a.z, a.w, b.x, b.y, b.z, b.w};
#pragma unroll
            for (int h = 0; h < 8; h++) {
                float x = ev[h] + er8[h];
                x = (x > 0.f) ? x : NEG_SLOPE * x;
                sm[h] += expf(x - mx[h]);
            }
        }
#pragma unroll
        for (int off = 16; off > 0; off >>= 1)
#pragma unroll
            for (int h = 0; h < 8; h++) sm[h] += __shfl_xor_sync(0xffffffffu, sm[h], off);

        float inv[8];
#pragma unroll
        for (int h = 0; h < 8; h++) inv[h] = 1.0f / (sm[h] + 1e-9f);

        // pass 3 (heavy): alpha + weighted feature accumulation, whole warp per edge
        int hsel = lane & 7;
        for (int idx = beg; idx < end; idx++) {
            int e = g_colidx[m][idx];               // warp-uniform
            int s = src[(size_t)m * NE + e];
            float x = el[(size_t)s * NH + hsel] + er8[hsel];
            x = (x > 0.f) ? x : NEG_SLOPE * x;
            float a_h = expf(x - mx[hsel]) * inv[hsel];
            if (lane < 8) out_alpha[((size_t)m * NE + e) * NH + lane] = a_h;
            const float4* f4 = (const float4*)(g_feat + ((size_t)m * NN + s) * DD);
#pragma unroll
            for (int j = 0; j < 4; j++) {
                int hh = 2 * j + (lane >> 4);
                float a = __shfl_sync(0xffffffffu, a_h, hh);
                float4 f = f4[lane + 32 * j];
                acc[j].x += a * f.x; acc[j].y += a * f.y;
                acc[j].z += a * f.z; acc[j].w += a * f.w;
            }
        }
    }

    // epilogue: elu(acc + bias) -> z[n][m][:]
    const float4* b4 = (const float4*)(bias + (size_t)m * DD);
    float4* zrow = (float4*)(g_z + ((size_t)n * MP + m) * DD);
#pragma unroll
    for (int j = 0; j < 4; j++) {
        float4 v = acc[j];
        float4 bb = b4[lane + 32 * j];
        v.x += bb.x; v.y += bb.y; v.z += bb.z; v.w += bb.w;
        v.x = (v.x > 0.f) ? v.x : expm1f(v.x);
        v.y = (v.y > 0.f) ? v.y : expm1f(v.y);
        v.z = (v.z > 0.f) ? v.z : expm1f(v.z);
        v.w = (v.w > 0.f) ? v.w : expm1f(v.w);
        zrow[lane + 32 * j] = v;
    }
}

// ---------------- semantic attention GEMM: tanh(z @ w1 + b1) @ w2, reduced over nodes ----------------
__global__ __launch_bounds__(256) void sem_kernel(const float* __restrict__ w1,
                                                  const float* __restrict__ b1,
                                                  const float* __restrict__ w2) {
    int r0 = blockIdx.x * 128;
    __shared__ float As[8][128];
    __shared__ float Bs[8][128];
    __shared__ float sred[128][16];

    int tid = threadIdx.x;
    int arow = tid >> 1;
    int acol = (tid & 1) * 4;
    int brow = tid >> 5;
    int bcol = (tid & 31) * 4;
    int ty = tid >> 4, tx = tid & 15;

    float acc[8][8];
#pragma unroll
    for (int i = 0; i < 8; i++)
#pragma unroll
        for (int j = 0; j < 8; j++) acc[i][j] = 0.0f;

    for (int k0 = 0; k0 < DD; k0 += 8) {
        float4 av = make_float4(0.f, 0.f, 0.f, 0.f);
        int ar = r0 + arow;
        if (ar < RROWS) av = *(const float4*)(g_z + (size_t)ar * DD + k0 + acol);
        As[acol + 0][arow] = av.x;
        As[acol + 1][arow] = av.y;
        As[acol + 2][arow] = av.z;
        As[acol + 3][arow] = av.w;
        *(float4*)&Bs[brow][bcol] = *(const float4*)(w1 + (size_t)(k0 + brow) * HID + bcol);
        __syncthreads();
#pragma unroll
        for (int k = 0; k < 8; k++) {
            float4 a0 = *(const float4*)&As[k][ty * 8];
            float4 a1 = *(const float4*)&As[k][ty * 8 + 4];
            float4 b0 = *(const float4*)&Bs[k][tx * 8];
            float4 b1v = *(const float4*)&Bs[k][tx * 8 + 4];
            float ra[8] = {a0.x, a0.y, a0.z, a0.w, a1.x, a1.y, a1.z, a1.w};
            float rb[8] = {b0.x, b0.y, b0.z, b0.w, b1v.x, b1v.y, b1v.z, b1v.w};
#pragma unroll
            for (int i = 0; i < 8; i++)
#pragma unroll
                for (int j = 0; j < 8; j++) acc[i][j] += ra[i] * rb[j];
        }
        __syncthreads();
    }

    // epilogue: per-row partial of tanh(acc + b1) . w2, reduce across tx, accumulate per-path
    float b1c[8], w2c[8];
#pragma unroll
    for (int j = 0; j < 8; j++) {
        int c = tx * 8 + j;
        b1c[j] = b1[c];
        w2c[j] = w2[c];
    }
#pragma unroll
    for (int i = 0; i < 8; i++) {
        float partial = 0.f;
#pragma unroll
        for (int j = 0; j < 8; j++) partial += tanhf(acc[i][j] + b1c[j]) * w2c[j];
        sred[ty * 8 + i][tx] = partial;
    }
    __syncthreads();
    if (tid < 128) {
        int gr = r0 + tid;
        if (gr < RROWS) {
            float s = 0.f;
#pragma unroll
            for (int x = 0; x < 16; x++) s += sred[tid][x];
            atomicAdd(&g_wsum[gr % MP], s);
        }
    }
}

// ---------------- beta: softmax over 3 path scores ----------------
__global__ void beta_kernel(float* __restrict__ out_beta) {
    if (threadIdx.x == 0 && blockIdx.x == 0) {
        float w[MP];
        float mx = -INFINITY;
        for (int m = 0; m < MP; m++) { w[m] = g_wsum[m] / (float)NN; mx = fmaxf(mx, w[m]); }
        float s = 0.f;
        for (int m = 0; m < MP; m++) { w[m] = expf(w[m] - mx); s += w[m]; }
        for (int m = 0; m < MP; m++) {
            float b = w[m] / s;
            g_beta[m] = b;
            out_beta[m] = b;
        }
    }
}

// ---------------- combine: gat_out = sum_m beta[m] * z[:,m,:] ----------------
__global__ void combine_kernel(float* __restrict__ out) {
    int i = blockIdx.x * 256 + threadIdx.x;   // float4 index over N*128
    if (i >= NN * 128) return;
    int n = i >> 7, c = i & 127;
    const float4* z4 = (const float4*)g_z;
    float b0 = g_beta[0], b1 = g_beta[1], b2 = g_beta[2];
    float4 v0 = z4[((size_t)n * MP + 0) * 128 + c];
    float4 v1 = z4[((size_t)n * MP + 1) * 128 + c];
    float4 v2 = z4[((size_t)n * MP + 2) * 128 + c];
    float4 r;
    r.x = b0 * v0.x + b1 * v1.x + b2 * v2.x;
    r.y = b0 * v0.y + b1 * v1.y + b2 * v2.y;
    r.z = b0 * v0.z + b1 * v1.z + b2 * v2.z;
    r.w = b0 * v0.w + b1 * v1.w + b2 * v2.w;
    ((float4*)out)[i] = r;
}

// ---------------- launch ----------------
extern "C" void kernel_launch(void* const* d_in, const int* in_sizes, int n_in,
                              void* d_out, int out_size) {
    const float* h      = (const float*)d_in[0];
    const float* W      = (const float*)d_in[1];
    const float* attn_l = (const float*)d_in[2];
    const float* attn_r = (const float*)d_in[3];
    const float* bias   = (const float*)d_in[4];
    const float* sem_w1 = (const float*)d_in[5];
    const float* sem_b1 = (const float*)d_in[6];
    const float* sem_w2 = (const float*)d_in[7];
    const int*   src    = (const int*)d_in[8];
    const int*   dst    = (const int*)d_in[9];

    float* out       = (float*)d_out;
    float* out_alpha = out + (size_t)NN * DD;
    float* out_beta  = out_alpha + (size_t)MP * NE * NH;

    // init
    init_kernel<<<(MP * NN + 255) / 256, 256>>>();

    // feat GEMM: grid (colblocks, rowblocks, paths)
    {
        dim3 g(DD / 128, (NN + 127) / 128, MP);
        gemm_feat_kernel<<<g, 256>>>(h, W);
    }

    // el / er
    el_er_kernel<<<(MP * NN + 7) / 8, 256>>>(attn_l, attn_r);

    // CSR build
    hist_kernel<<<(MP * NE + 255) / 256, 256>>>(dst);
    {
        dim3 g((NN + 1023) / 1024, MP);
        scanA_kernel<<<g, 256>>>();
    }
    scanB_kernel<<<MP, 32>>>();
    {
        dim3 g((NN + 255) / 256, MP);
        scanC_kernel<<<g, 256>>>();
    }
    scatter_kernel<<<(MP * NE + 255) / 256, 256>>>(dst);

    // per-destination softmax + aggregation
    {
        dim3 g((NN + 7) / 8, MP);
        gather_kernel<<<g, 256>>>(src, bias, out_alpha);
    }

    // semantic attention
    sem_kernel<<<(RROWS + 127) / 128, 256>>>(sem_w1, sem_b1, sem_w2);
    beta_kernel<<<1, 32>>>(out_beta);
    combine_kernel<<<(NN * 128 + 255) / 256, 256>>>(out);
}

// round 12
// speedup vs baseline: 1.3954x; 1.3954x over previous
#include <cuda_runtime.h>
#include <cuda_bf16.h>
#include <math.h>

#define NN   20000      // nodes
#define NE   256000     // edges per path
#define MP   3          // metapaths
#define INS  256        // in feature size
#define NH   8          // heads
#define FH   64         // out per head
#define DD   512        // NH*FH
#define HID  128
#define NEG_SLOPE 0.2f
#define RROWS (NN*MP)
#define MB1  ((NN + 127) / 128)     // 157

// ---------------- scratch (device globals; no cudaMalloc allowed) ----------------
__device__ float g_feat[(size_t)MP * NN * DD];   // [m][n][d]
__device__ float g_z[(size_t)NN * MP * DD];      // [n][m][d]
__device__ float g_el[MP * NN * NH];
__device__ float g_er[MP * NN * NH];
__device__ int   g_rowptr[MP][NN + 1];
__device__ int   g_cnt[MP][NN];
__device__ int   g_colidx[MP][NE];
__device__ int   g_part[MP][64];
__device__ float g_wsum[MP];
__device__ float g_beta[MP];

// ---------------- helpers ----------------
__device__ __forceinline__ void mma_bf16(float* c, const unsigned* a, const unsigned* b) {
    asm volatile(
        "mma.sync.aligned.m16n8k16.row.col.f32.bf16.bf16.f32 "
        "{%0,%1,%2,%3}, {%4,%5,%6,%7}, {%8,%9}, {%0,%1,%2,%3};\n"
        : "+f"(c[0]), "+f"(c[1]), "+f"(c[2]), "+f"(c[3])
        : "r"(a[0]), "r"(a[1]), "r"(a[2]), "r"(a[3]), "r"(b[0]), "r"(b[1]));
}

__device__ __forceinline__ void split2(float x, __nv_bfloat16& hi, __nv_bfloat16& lo) {
    hi = __float2bfloat16_rn(x);
    lo = __float2bfloat16_rn(x - __bfloat162float(hi));
}

// ---------------- init ----------------
__global__ void init_kernel() {
    int i = blockIdx.x * 256 + threadIdx.x;
    if (i < MP * NN) ((int*)g_cnt)[i] = 0;
    if (i < MP) g_wsum[i] = 0.0f;
}

// ================= GEMM1 (tensor core, bf16x3): feat[m] = h @ W[m] =================
// Tile 128x128x16. 8 warps: 2(m) x 4(n), warp tile 64x32.
#define SPAD 18
__global__ __launch_bounds__(256) void gemm_feat_mma(const float* __restrict__ hmat,
                                                     const float* __restrict__ Wmat) {
    __shared__ __nv_bfloat16 Ab[128][SPAD], Al[128][SPAD];
    __shared__ __nv_bfloat16 Bb[128][SPAD], Bl[128][SPAD];

    int m = blockIdx.z;
    const float* B = Wmat + (size_t)m * INS * DD;
    float* C = g_feat + (size_t)m * NN * DD;

    int tid = threadIdx.x;
    int row0 = blockIdx.y * 128;
    int col0 = blockIdx.x * 128;

    int wid = tid >> 5, lane = tid & 31;
    int g = lane >> 2, t = lane & 3;
    int wm = (wid >> 2) * 64, wn = (wid & 3) * 32;

    // global load addressing
    int ar = tid >> 2;                 // A rows ar, ar+64
    int ac = (tid & 3) * 4;            // A col4
    int bk = tid >> 5;                 // B k-rows bk, bk+8
    int bc = (tid & 31) * 4;           // B col4

    float acc[4][4][4];
#pragma unroll
    for (int i = 0; i < 4; i++)
#pragma unroll
        for (int j = 0; j < 4; j++)
#pragma unroll
            for (int q = 0; q < 4; q++) acc[i][j][q] = 0.0f;

    float4 a0v, a1v, b0v, b1v;
    // prefetch tile 0
    {
        int r0a = row0 + ar, r1a = row0 + ar + 64;
        a0v = (r0a < NN) ? *(const float4*)(hmat + (size_t)r0a * INS + ac) : make_float4(0,0,0,0);
        a1v = (r1a < NN) ? *(const float4*)(hmat + (size_t)r1a * INS + ac) : make_float4(0,0,0,0);
        b0v = *(const float4*)(B + (size_t)bk * DD + col0 + bc);
        b1v = *(const float4*)(B + (size_t)(bk + 8) * DD + col0 + bc);
    }

    const int NK = INS / 16;  // 16
    for (int kt = 0; kt < NK; kt++) {
        // store prefetched regs -> smem (split hi/lo)
        {
            float va[4] = {a0v.x, a0v.y, a0v.z, a0v.w};
            float vb[4] = {a1v.x, a1v.y, a1v.z, a1v.w};
#pragma unroll
            for (int j = 0; j < 4; j++) {
                __nv_bfloat16 hi, lo;
                split2(va[j], hi, lo); Ab[ar][ac + j] = hi; Al[ar][ac + j] = lo;
                split2(vb[j], hi, lo); Ab[ar + 64][ac + j] = hi; Al[ar + 64][ac + j] = lo;
            }
            float vc[4] = {b0v.x, b0v.y, b0v.z, b0v.w};
            float vd[4] = {b1v.x, b1v.y, b1v.z, b1v.w};
#pragma unroll
            for (int j = 0; j < 4; j++) {
                __nv_bfloat16 hi, lo;
                split2(vc[j], hi, lo); Bb[bc + j][bk] = hi; Bl[bc + j][bk] = lo;
                split2(vd[j], hi, lo); Bb[bc + j][bk + 8] = hi; Bl[bc + j][bk + 8] = lo;
            }
        }
        __syncthreads();

        // prefetch next tile
        if (kt + 1 < NK) {
            int k0 = (kt + 1) * 16;
            int r0a = row0 + ar, r1a = row0 + ar + 64;
            a0v = (r0a < NN) ? *(const float4*)(hmat + (size_t)r0a * INS + k0 + ac) : make_float4(0,0,0,0);
            a1v = (r1a < NN) ? *(const float4*)(hmat + (size_t)r1a * INS + k0 + ac) : make_float4(0,0,0,0);
            b0v = *(const float4*)(B + (size_t)(k0 + bk) * DD + col0 + bc);
            b1v = *(const float4*)(B + (size_t)(k0 + bk + 8) * DD + col0 + bc);
        }

        // fragments
        unsigned fab[4][4], fal[4][4];
#pragma unroll
        for (int mi = 0; mi < 4; mi++) {
            int r = wm + mi * 16 + g;
            fab[mi][0] = *(const unsigned*)&Ab[r][2 * t];
            fab[mi][1] = *(const unsigned*)&Ab[r + 8][2 * t];
            fab[mi][2] = *(const unsigned*)&Ab[r][2 * t + 8];
            fab[mi][3] = *(const unsigned*)&Ab[r + 8][2 * t + 8];
            fal[mi][0] = *(const unsigned*)&Al[r][2 * t];
            fal[mi][1] = *(const unsigned*)&Al[r + 8][2 * t];
            fal[mi][2] = *(const unsigned*)&Al[r][2 * t + 8];
            fal[mi][3] = *(const unsigned*)&Al[r + 8][2 * t + 8];
        }
        unsigned fbb[4][2], fbl[4][2];
#pragma unroll
        for (int ni = 0; ni < 4; ni++) {
            int c = wn + ni * 8 + g;
            fbb[ni][0] = *(const unsigned*)&Bb[c][2 * t];
            fbb[ni][1] = *(const unsigned*)&Bb[c][2 * t + 8];
            fbl[ni][0] = *(const unsigned*)&Bl[c][2 * t];
            fbl[ni][1] = *(const unsigned*)&Bl[c][2 * t + 8];
        }
#pragma unroll
        for (int mi = 0; mi < 4; mi++)
#pragma unroll
            for (int ni = 0; ni < 4; ni++) {
                mma_bf16(acc[mi][ni], fab[mi], fbb[ni]);   // hi*hi
                mma_bf16(acc[mi][ni], fab[mi], fbl[ni]);   // hi*lo
                mma_bf16(acc[mi][ni], fal[mi], fbb[ni]);   // lo*hi
            }
        __syncthreads();
    }

    // epilogue: write C
#pragma unroll
    for (int mi = 0; mi < 4; mi++) {
        int r = row0 + wm + mi * 16 + g;
#pragma unroll
        for (int ni = 0; ni < 4; ni++) {
            int c = col0 + wn + ni * 8 + 2 * t;
            if (r < NN)     *(float2*)(C + (size_t)r * DD + c)       = make_float2(acc[mi][ni][0], acc[mi][ni][1]);
            if (r + 8 < NN) *(float2*)(C + (size_t)(r + 8) * DD + c) = make_float2(acc[mi][ni][2], acc[mi][ni][3]);
        }
    }
}

// ================= semantic GEMM (tensor core, bf16x3) + fused tanh/w2 reduction =================
// rows = g_z [RROWS x DD], B = sem_w1 [DD x HID]. BN = HID = 128 (col0 = 0).
__global__ __launch_bounds__(256) void sem_mma(const float* __restrict__ w1,
                                               const float* __restrict__ b1,
                                               const float* __restrict__ w2) {
    __shared__ __nv_bfloat16 Ab[128][SPAD], Al[128][SPAD];
    __shared__ __nv_bfloat16 Bb[128][SPAD], Bl[128][SPAD];
    __shared__ float sred[128];
    __shared__ float spath[MP];

    int tid = threadIdx.x;
    int row0 = blockIdx.x * 128;

    if (tid < 128) sred[tid] = 0.0f;
    if (tid < MP) spath[tid] = 0.0f;

    int wid = tid >> 5, lane = tid & 31;
    int g = lane >> 2, t = lane & 3;
    int wm = (wid >> 2) * 64, wn = (wid & 3) * 32;

    int ar = tid >> 2;
    int ac = (tid & 3) * 4;
    int bk = tid >> 5;
    int bc = (tid & 31) * 4;

    float acc[4][4][4];
#pragma unroll
    for (int i = 0; i < 4; i++)
#pragma unroll
        for (int j = 0; j < 4; j++)
#pragma unroll
            for (int q = 0; q < 4; q++) acc[i][j][q] = 0.0f;

    float4 a0v, a1v, b0v, b1v;
    {
        int r0a = row0 + ar, r1a = row0 + ar + 64;
        a0v = (r0a < RROWS) ? *(const float4*)(g_z + (size_t)r0a * DD + ac) : make_float4(0,0,0,0);
        a1v = (r1a < RROWS) ? *(const float4*)(g_z + (size_t)r1a * DD + ac) : make_float4(0,0,0,0);
        b0v = *(const float4*)(w1 + (size_t)bk * HID + bc);
        b1v = *(const float4*)(w1 + (size_t)(bk + 8) * HID + bc);
    }

    const int NK = DD / 16;  // 32
    for (int kt = 0; kt < NK; kt++) {
        {
            float va[4] = {a0v.x, a0v.y, a0v.z, a0v.w};
            float vb[4] = {a1v.x, a1v.y, a1v.z, a1v.w};
#pragma unroll
            for (int j = 0; j < 4; j++) {
                __nv_bfloat16 hi, lo;
                split2(va[j], hi, lo); Ab[ar][ac + j] = hi; Al[ar][ac + j] = lo;
                split2(vb[j], hi, lo); Ab[ar + 64][ac + j] = hi; Al[ar + 64][ac + j] = lo;
            }
            float vc[4] = {b0v.x, b0v.y, b0v.z, b0v.w};
            float vd[4] = {b1v.x, b1v.y, b1v.z, b1v.w};
#pragma unroll
            for (int j = 0; j < 4; j++) {
                __nv_bfloat16 hi, lo;
                split2(vc[j], hi, lo); Bb[bc + j][bk] = hi; Bl[bc + j][bk] = lo;
                split2(vd[j], hi, lo); Bb[bc + j][bk + 8] = hi; Bl[bc + j][bk + 8] = lo;
            }
        }
        __syncthreads();

        if (kt + 1 < NK) {
            int k0 = (kt + 1) * 16;
            int r0a = row0 + ar, r1a = row0 + ar + 64;
            a0v = (r0a < RROWS) ? *(const float4*)(g_z + (size_t)r0a * DD + k0 + ac) : make_float4(0,0,0,0);
            a1v = (r1a < RROWS) ? *(const float4*)(g_z + (size_t)r1a * DD + k0 + ac) : make_float4(0,0,0,0);
            b0v = *(const float4*)(w1 + (size_t)(k0 + bk) * HID + bc);
            b1v = *(const float4*)(w1 + (size_t)(k0 + bk + 8) * HID + bc);
        }

        unsigned fab[4][4], fal[4][4];
#pragma unroll
        for (int mi = 0; mi < 4; mi++) {
            int r = wm + mi * 16 + g;
            fab[mi][0] = *(const unsigned*)&Ab[r][2 * t];
            fab[mi][1] = *(const unsigned*)&Ab[r + 8][2 * t];
            fab[mi][2] = *(const unsigned*)&Ab[r][2 * t + 8];
            fab[mi][3] = *(const unsigned*)&Ab[r + 8][2 * t + 8];
            fal[mi][0] = *(const unsigned*)&Al[r][2 * t];
            fal[mi][1] = *(const unsigned*)&Al[r + 8][2 * t];
            fal[mi][2] = *(const unsigned*)&Al[r][2 * t + 8];
            fal[mi][3] = *(const unsigned*)&Al[r + 8][2 * t + 8];
        }
        unsigned fbb[4][2], fbl[4][2];
#pragma unroll
        for (int ni = 0; ni < 4; ni++) {
            int c = wn + ni * 8 + g;
            fbb[ni][0] = *(const unsigned*)&Bb[c][2 * t];
            fbb[ni][1] = *(const unsigned*)&Bb[c][2 * t + 8];
            fbl[ni][0] = *(const unsigned*)&Bl[c][2 * t];
            fbl[ni][1] = *(const unsigned*)&Bl[c][2 * t + 8];
        }
#pragma unroll
        for (int mi = 0; mi < 4; mi++)
#pragma unroll
            for (int ni = 0; ni < 4; ni++) {
                mma_bf16(acc[mi][ni], fab[mi], fbb[ni]);
                mma_bf16(acc[mi][ni], fab[mi], fbl[ni]);
                mma_bf16(acc[mi][ni], fal[mi], fbb[ni]);
            }
        __syncthreads();
    }

    // epilogue: per-row sum of tanh(c + b1) * w2, accumulate into per-path sums
#pragma unroll
    for (int mi = 0; mi < 4; mi++) {
        float s0 = 0.f, s1 = 0.f;
#pragma unroll
        for (int ni = 0; ni < 4; ni++) {
            int c = wn + ni * 8 + 2 * t;
            float w2a = w2[c], w2b = w2[c + 1];
            float b1a = b1[c], b1b = b1[c + 1];
            s0 += tanhf(acc[mi][ni][0] + b1a) * w2a + tanhf(acc[mi][ni][1] + b1b) * w2b;
            s1 += tanhf(acc[mi][ni][2] + b1a) * w2a + tanhf(acc[mi][ni][3] + b1b) * w2b;
        }
        s0 += __shfl_xor_sync(0xffffffffu, s0, 1);
        s0 += __shfl_xor_sync(0xffffffffu, s0, 2);
        s1 += __shfl_xor_sync(0xffffffffu, s1, 1);
        s1 += __shfl_xor_sync(0xffffffffu, s1, 2);
        if (t == 0) {
            atomicAdd(&sred[wm + mi * 16 + g], s0);
            atomicAdd(&sred[wm + mi * 16 + g + 8], s1);
        }
    }
    __syncthreads();
    if (tid < 128) {
        int gr = row0 + tid;
        if (gr < RROWS) atomicAdd(&spath[gr % MP], sred[tid]);
    }
    __syncthreads();
    if (tid < MP) atomicAdd(&g_wsum[tid], spath[tid]);
}

// ---------------- el/er: per (path,node) head dot products; one warp each ----------------
__global__ void el_er_kernel(const float* __restrict__ attn_l, const float* __restrict__ attn_r) {
    int gw = blockIdx.x * 8 + (threadIdx.x >> 5);
    if (gw >= MP * NN) return;
    int m = gw / NN, n = gw % NN;
    int lane = threadIdx.x & 31;
    const float* frow = g_feat + ((size_t)m * NN + n) * DD;

    float pl[8], pr[8];
#pragma unroll
    for (int h = 0; h < 8; h++) { pl[h] = 0.f; pr[h] = 0.f; }
#pragma unroll
    for (int j = 0; j < 16; j++) {
        int c = lane + 32 * j;
        int hh = j >> 1;
        int fi = lane + 32 * (j & 1);
        float f = frow[c];
        pl[hh] += f * attn_l[(m * NH + hh) * FH + fi];
        pr[hh] += f * attn_r[(m * NH + hh) * FH + fi];
    }
#pragma unroll
    for (int off = 16; off > 0; off >>= 1) {
#pragma unroll
        for (int h = 0; h < 8; h++) {
            pl[h] += __shfl_xor_sync(0xffffffffu, pl[h], off);
            pr[h] += __shfl_xor_sync(0xffffffffu, pr[h], off);
        }
    }
    if (lane < 8) {
        g_el[((size_t)m * NN + n) * NH + lane] = pl[lane];
        g_er[((size_t)m * NN + n) * NH + lane] = pr[lane];
    }
}

// ---------------- CSR build ----------------
__global__ void hist_kernel(const int* __restrict__ dst) {
    int i = blockIdx.x * 256 + threadIdx.x;
    if (i >= MP * NE) return;
    int m = i / NE;
    atomicAdd(&g_cnt[m][dst[i]], 1);
}

__global__ void scanA_kernel() {
    int m = blockIdx.y;
    int c0 = blockIdx.x * 1024;
    int tid = threadIdx.x;
    __shared__ int s[256];
    int v[4]; int sum = 0;
#pragma unroll
    for (int t = 0; t < 4; t++) {
        int i = c0 + tid * 4 + t;
        v[t] = (i < NN) ? g_cnt[m][i] : 0;
        sum += v[t];
    }
    s[tid] = sum;
    __syncthreads();
    for (int off = 1; off < 256; off <<= 1) {
        int t = (tid >= off) ? s[tid - off] : 0;
        __syncthreads();
        s[tid] += t;
        __syncthreads();
    }
    int run = s[tid] - sum;
#pragma unroll
    for (int t = 0; t < 4; t++) {
        int i = c0 + tid * 4 + t;
        if (i < NN) g_rowptr[m][i] = run;
        run += v[t];
    }
    if (tid == 255) g_part[m][blockIdx.x] = s[255];
}

__global__ void scanB_kernel() {
    int m = blockIdx.x;
    if (threadIdx.x == 0) {
        int run = 0;
        const int nchunk = (NN + 1023) / 1024;
        for (int c = 0; c < nchunk; c++) { int t = g_part[m][c]; g_part[m][c] = run; run += t; }
    }
}

__global__ void scanC_kernel() {
    int m = blockIdx.y;
    int i = blockIdx.x * 256 + threadIdx.x;
    if (i < NN) {
        g_rowptr[m][i] += g_part[m][i >> 10];
        g_cnt[m][i] = 0;
    }
    if (i == 0) g_rowptr[m][NN] = NE;
}

__global__ void scatter_kernel(const int* __restrict__ dst) {
    int i = blockIdx.x * 256 + threadIdx.x;
    if (i >= MP * NE) return;
    int m = i / NE, e = i % NE;
    int d = dst[i];
    int pos = g_rowptr[m][d] + atomicAdd(&g_cnt[m][d], 1);
    g_colidx[m][pos] = e;
}

// ---------------- gather: per-dst softmax + weighted aggregation. One warp per (n,m). ----------------
__global__ __launch_bounds__(256) void gather_kernel(const int* __restrict__ src,
                                                     const float* __restrict__ bias,
                                                     float* __restrict__ out_alpha) {
    int m = blockIdx.y;
    int n = blockIdx.x * 8 + (threadIdx.x >> 5);
    if (n >= NN) return;
    int lane = threadIdx.x & 31;

    int beg = g_rowptr[m][n];
    int end = g_rowptr[m][n + 1];

    const float* el = g_el + (size_t)m * NN * NH;
    float er8[8];
    {
        const float4* e4 = (const float4*)(g_er + ((size_t)m * NN + n) * NH);
        float4 a = e4[0], b = e4[1];
        er8[0] = a.x; er8[1] = a.y; er8[2] = a.z; er8[3] = a.w;
        er8[4] = b.x; er8[5] = b.y; er8[6] = b.z; er8[7] = b.w;
    }

    float4 acc[4];
#pragma unroll
    for (int j = 0; j < 4; j++) acc[j] = make_float4(0.f, 0.f, 0.f, 0.f);

    if (end > beg) {
        float mx[8];
#pragma unroll
        for (int h = 0; h < 8; h++) mx[h] = -INFINITY;
        for (int idx = beg + lane; idx < end; idx += 32) {
            int e = g_colidx[m][idx];
            int s = src[(size_t)m * NE + e];
            const float4* s4 = (const float4*)(el + (size_t)s * NH);
            float4 a = s4[0], b = s4[1];
            float ev[8] = {a.x, a.y, a.z, a.w, b.x, b.y, b.z, b.w};
#pragma unroll
            for (int h = 0; h < 8; h++) {
                float x = ev[h] + er8[h];
                x = (x > 0.f) ? x : NEG_SLOPE * x;
                mx[h] = fmaxf(mx[h], x);
            }
        }
#pragma unroll
        for (int off = 16; off > 0; off >>= 1)
#pragma unroll
            for (int h = 0; h < 8; h++) mx[h] = fmaxf(mx[h], __shfl_xor_sync(0xffffffffu, mx[h], off));

        float sm[8];
#pragma unroll
        for (int h = 0; h < 8; h++) sm[h] = 0.f;
        for (int idx = beg + lane; idx < end; idx += 32) {
            int e = g_colidx[m][idx];
            int s = src[(size_t)m * NE + e];
            const float4* s4 = (const float4*)(el + (size_t)s * NH);
            float4 a = s4[0], b = s4[1];
            float ev[8] = {a.x, a.y, a.z, a.w, b.x, b.y, b.z, b.w};
#pragma unroll
            for (int h = 0; h < 8; h++) {
                float x = ev[h] + er8[h];
                x = (x > 0.f) ? x : NEG_SLOPE * x;
                sm[h] += expf(x - mx[h]);
            }
        }
#pragma unroll
        for (int off = 16; off > 0; off >>= 1)
#pragma unroll
            for (int h = 0; h < 8; h++) sm[h] += __shfl_xor_sync(0xffffffffu, sm[h], off);

        float inv[8];
#pragma unroll
        for (int h = 0; h < 8; h++) inv[h] = 1.0f / (sm[h] + 1e-9f);

        int hsel = lane & 7;
        for (int idx = beg; idx < end; idx++) {
            int e = g_colidx[m][idx];
            int s = src[(size_t)m * NE + e];
            float x = el[(size_t)s * NH + hsel] + er8[hsel];
            x = (x > 0.f) ? x : NEG_SLOPE * x;
            float a_h = expf(x - mx[hsel]) * inv[hsel];
            if (lane < 8) out_alpha[((size_t)m * NE + e) * NH + lane] = a_h;
            const float4* f4 = (const float4*)(g_feat + ((size_t)m * NN + s) * DD);
#pragma unroll
            for (int j = 0; j < 4; j++) {
                int hh = 2 * j + (lane >> 4);
                float a = __shfl_sync(0xffffffffu, a_h, hh);
                float4 f = f4[lane + 32 * j];
                acc[j].x += a * f.x; acc[j].y += a * f.y;
                acc[j].z += a * f.z; acc[j].w += a * f.w;
            }
        }
    }

    const float4* b4 = (const float4*)(bias + (size_t)m * DD);
    float4* zrow = (float4*)(g_z + ((size_t)n * MP + m) * DD);
#pragma unroll
    for (int j = 0; j < 4; j++) {
        float4 v = acc[j];
        float4 bb = b4[lane + 32 * j];
        v.x += bb.x; v.y += bb.y; v.z += bb.z; v.w += bb.w;
        v.x = (v.x > 0.f) ? v.x : expm1f(v.x);
        v.y = (v.y > 0.f) ? v.y : expm1f(v.y);
        v.z = (v.z > 0.f) ? v.z : expm1f(v.z);
        v.w = (v.w > 0.f) ? v.w : expm1f(v.w);
        zrow[lane + 32 * j] = v;
    }
}

// ---------------- beta ----------------
__global__ void beta_kernel(float* __restrict__ out_beta) {
    if (threadIdx.x == 0 && blockIdx.x == 0) {
        float w[MP];
        float mx = -INFINITY;
        for (int m = 0; m < MP; m++) { w[m] = g_wsum[m] / (float)NN; mx = fmaxf(mx, w[m]); }
        float s = 0.f;
        for (int m = 0; m < MP; m++) { w[m] = expf(w[m] - mx); s += w[m]; }
        for (int m = 0; m < MP; m++) {
            float b = w[m] / s;
            g_beta[m] = b;
            out_beta[m] = b;
        }
    }
}

// ---------------- combine ----------------
__global__ void combine_kernel(float* __restrict__ out) {
    int i = blockIdx.x * 256 + threadIdx.x;
    if (i >= NN * 128) return;
    int n = i >> 7, c = i & 127;
    const float4* z4 = (const float4*)g_z;
    float b0 = g_beta[0], b1 = g_beta[1], b2 = g_beta[2];
    float4 v0 = z4[((size_t)n * MP + 0) * 128 + c];
    float4 v1 = z4[((size_t)n * MP + 1) * 128 + c];
    float4 v2 = z4[((size_t)n * MP + 2) * 128 + c];
    float4 r;
    r.x = b0 * v0.x + b1 * v1.x + b2 * v2.x;
    r.y = b0 * v0.y + b1 * v1.y + b2 * v2.y;
    r.z = b0 * v0.z + b1 * v1.z + b2 * v2.z;
    r.w = b0 * v0.w + b1 * v1.w + b2 * v2.w;
    ((float4*)out)[i] = r;
}

// ---------------- launch ----------------
extern "C" void kernel_launch(void* const* d_in, const int* in_sizes, int n_in,
                              void* d_out, int out_size) {
    const float* h      = (const float*)d_in[0];
    const float* W      = (const float*)d_in[1];
    const float* attn_l = (const float*)d_in[2];
    const float* attn_r = (const float*)d_in[3];
    const float* bias   = (const float*)d_in[4];
    const float* sem_w1 = (const float*)d_in[5];
    const float* sem_b1 = (const float*)d_in[6];
    const float* sem_w2 = (const float*)d_in[7];
    const int*   src    = (const int*)d_in[8];
    const int*   dst    = (const int*)d_in[9];

    float* out       = (float*)d_out;
    float* out_alpha = out + (size_t)NN * DD;
    float* out_beta  = out_alpha + (size_t)MP * NE * NH;

    init_kernel<<<(MP * NN + 255) / 256, 256>>>();

    {
        dim3 g(DD / 128, MB1, MP);
        gemm_feat_mma<<<g, 256>>>(h, W);
    }

    el_er_kernel<<<(MP * NN + 7) / 8, 256>>>(attn_l, attn_r);

    hist_kernel<<<(MP * NE + 255) / 256, 256>>>(dst);
    {
        dim3 g((NN + 1023) / 1024, MP);
        scanA_kernel<<<g, 256>>>();
    }
    scanB_kernel<<<MP, 32>>>();
    {
        dim3 g((NN + 255) / 256, MP);
        scanC_kernel<<<g, 256>>>();
    }
    scatter_kernel<<<(MP * NE + 255) / 256, 256>>>(dst);

    {
        dim3 g((NN + 7) / 8, MP);
        gather_kernel<<<g, 256>>>(src, bias, out_alpha);
    }

    sem_mma<<<(RROWS + 127) / 128, 256>>>(sem_w1, sem_b1, sem_w2);
    beta_kernel<<<1, 32>>>(out_beta);
    combine_kernel<<<(NN * 128 + 255) / 256, 256>>>(out);
}

// round 15
// speedup vs baseline: 1.4589x; 1.0456x over previous
#include <cuda_runtime.h>
#include <cuda_bf16.h>
#include <math.h>

#define NN   20000      // nodes
#define NE   256000     // edges per path
#define MP   3          // metapaths
#define INS  256        // in feature size
#define NH   8          // heads
#define FH   64         // out per head
#define DD   512        // NH*FH
#define HID  128
#define NEG_SLOPE 0.2f
#define RROWS (NN*MP)
#define MB1  ((NN + 127) / 128)     // 157

// ---------------- scratch (device globals; no cudaMalloc allowed) ----------------
__device__ float g_feat[(size_t)MP * NN * DD];   // [m][n][d] fp32 (needed by el_er/gather)
__device__ __nv_bfloat16 g_h_hi[(size_t)NN * INS],  g_h_lo[(size_t)NN * INS];     // split h
__device__ __nv_bfloat16 g_wt_hi[(size_t)MP * DD * INS], g_wt_lo[(size_t)MP * DD * INS]; // W^T [m][n][k]
__device__ __nv_bfloat16 g_w1t_hi[(size_t)HID * DD], g_w1t_lo[(size_t)HID * DD];  // w1^T [n][k]
__device__ __nv_bfloat16 g_zb[(size_t)RROWS * DD], g_zl[(size_t)RROWS * DD];      // z split hi/lo
__device__ float g_el[MP * NN * NH];
__device__ float g_er[MP * NN * NH];
__device__ int   g_rowptr[MP][NN + 1];
__device__ int   g_cnt[MP][NN];
__device__ int   g_colidx[MP][NE];
__device__ int   g_part[MP][64];
__device__ float g_wsum[MP];
__device__ float g_beta[MP];

// ---------------- helpers ----------------
__device__ __forceinline__ void mma_bf16(float* c, const unsigned* a, const unsigned* b) {
    asm volatile(
        "mma.sync.aligned.m16n8k16.row.col.f32.bf16.bf16.f32 "
        "{%0,%1,%2,%3}, {%4,%5,%6,%7}, {%8,%9}, {%0,%1,%2,%3};\n"
        : "+f"(c[0]), "+f"(c[1]), "+f"(c[2]), "+f"(c[3])
        : "r"(a[0]), "r"(a[1]), "r"(a[2]), "r"(a[3]), "r"(b[0]), "r"(b[1]));
}

__device__ __forceinline__ void split2(float x, __nv_bfloat16& hi, __nv_bfloat16& lo) {
    hi = __float2bfloat16_rn(x);
    lo = __float2bfloat16_rn(x - __bfloat162float(hi));
}

__device__ __forceinline__ unsigned pack2(__nv_bfloat16 a, __nv_bfloat16 b) {
    return (unsigned)__bfloat16_as_ushort(a) | ((unsigned)__bfloat16_as_ushort(b) << 16);
}

// ---------------- init ----------------
__global__ void init_kernel() {
    int i = blockIdx.x * 256 + threadIdx.x;
    if (i < MP * NN) ((int*)g_cnt)[i] = 0;
    if (i < MP) g_wsum[i] = 0.0f;
}

// ---------------- split kernels ----------------
__global__ void split_h_kernel(const float* __restrict__ h) {
    int i = blockIdx.x * 256 + threadIdx.x;   // float4 group
    if (i >= NN * INS / 4) return;
    float4 v = ((const float4*)h)[i];
    __nv_bfloat16 h0,h1,h2,h3,l0,l1,l2,l3;
    split2(v.x,h0,l0); split2(v.y,h1,l1); split2(v.z,h2,l2); split2(v.w,h3,l3);
    ((uint2*)g_h_hi)[i] = make_uint2(pack2(h0,h1), pack2(h2,h3));
    ((uint2*)g_h_lo)[i] = make_uint2(pack2(l0,l1), pack2(l2,l3));
}

__global__ void split_W_kernel(const float* __restrict__ W) {
    int i = blockIdx.x * 256 + threadIdx.x;   // element over MP*INS*DD
    if (i >= MP * INS * DD) return;
    int m = i / (INS * DD);
    int rem = i - m * (INS * DD);
    int k = rem / DD, n = rem % DD;
    __nv_bfloat16 hi, lo;
    split2(W[i], hi, lo);
    size_t o = ((size_t)m * DD + n) * INS + k;
    g_wt_hi[o] = hi; g_wt_lo[o] = lo;
}

__global__ void split_w1_kernel(const float* __restrict__ w1) {
    int i = blockIdx.x * 256 + threadIdx.x;   // element over DD*HID
    if (i >= DD * HID) return;
    int k = i / HID, n = i % HID;
    __nv_bfloat16 hi, lo;
    split2(w1[i], hi, lo);
    size_t o = (size_t)n * DD + k;
    g_w1t_hi[o] = hi; g_w1t_lo[o] = lo;
}

// ================= GEMM1 (tensor core, bf16x3, pre-split inputs) =================
// Tile 128x128x16. 8 warps: 2(m) x 4(n), warp tile 64x32.
#define SPAD 24
__global__ __launch_bounds__(256) void gemm_feat_mma(int dummy) {
    __shared__ __nv_bfloat16 Ab[128][SPAD], Al[128][SPAD];
    __shared__ __nv_bfloat16 Bb[128][SPAD], Bl[128][SPAD];

    int m = blockIdx.z;
    float* C = g_feat + (size_t)m * NN * DD;

    int tid = threadIdx.x;
    int row0 = blockIdx.y * 128;
    int col0 = blockIdx.x * 128;

    int wid = tid >> 5, lane = tid & 31;
    int g = lane >> 2, t = lane & 3;
    int wm = (wid >> 2) * 64, wn = (wid & 3) * 32;

    int arow = tid >> 1;        // 0..127 (row within tile, both A and B)
    int ahalf = tid & 1;        // 0/1 -> 8-bf16 half of the 16-wide k window

    float acc[4][4][4];
#pragma unroll
    for (int i = 0; i < 4; i++)
#pragma unroll
        for (int j = 0; j < 4; j++)
#pragma unroll
            for (int q = 0; q < 4; q++) acc[i][j][q] = 0.0f;

    const uint4 z4 = make_uint4(0u,0u,0u,0u);
    uint4 a_hi, a_lo, b_hi, b_lo;
    // prefetch tile 0
    {
        int r = row0 + arow;
        size_t aoff = (size_t)r * INS + ahalf * 8;
        a_hi = (r < NN) ? *(const uint4*)(g_h_hi + aoff) : z4;
        a_lo = (r < NN) ? *(const uint4*)(g_h_lo + aoff) : z4;
        size_t boff = ((size_t)m * DD + col0 + arow) * INS + ahalf * 8;
        b_hi = *(const uint4*)(g_wt_hi + boff);
        b_lo = *(const uint4*)(g_wt_lo + boff);
    }

    const int NK = INS / 16;  // 16
    for (int kt = 0; kt < NK; kt++) {
        *(uint4*)&Ab[arow][ahalf * 8] = a_hi;
        *(uint4*)&Al[arow][ahalf * 8] = a_lo;
        *(uint4*)&Bb[arow][ahalf * 8] = b_hi;
        *(uint4*)&Bl[arow][ahalf * 8] = b_lo;
        __syncthreads();

        if (kt + 1 < NK) {
            int k0 = (kt + 1) * 16;
            int r = row0 + arow;
            size_t aoff = (size_t)r * INS + k0 + ahalf * 8;
            a_hi = (r < NN) ? *(const uint4*)(g_h_hi + aoff) : z4;
            a_lo = (r < NN) ? *(const uint4*)(g_h_lo + aoff) : z4;
            size_t boff = ((size_t)m * DD + col0 + arow) * INS + k0 + ahalf * 8;
            b_hi = *(const uint4*)(g_wt_hi + boff);
            b_lo = *(const uint4*)(g_wt_lo + boff);
        }

        unsigned fab[4][4], fal[4][4];
#pragma unroll
        for (int mi = 0; mi < 4; mi++) {
            int r = wm + mi * 16 + g;
            fab[mi][0] = *(const unsigned*)&Ab[r][2 * t];
            fab[mi][1] = *(const unsigned*)&Ab[r + 8][2 * t];
            fab[mi][2] = *(const unsigned*)&Ab[r][2 * t + 8];
            fab[mi][3] = *(const unsigned*)&Ab[r + 8][2 * t + 8];
            fal[mi][0] = *(const unsigned*)&Al[r][2 * t];
            fal[mi][1] = *(const unsigned*)&Al[r + 8][2 * t];
            fal[mi][2] = *(const unsigned*)&Al[r][2 * t + 8];
            fal[mi][3] = *(const unsigned*)&Al[r + 8][2 * t + 8];
        }
        unsigned fbb[4][2], fbl[4][2];
#pragma unroll
        for (int ni = 0; ni < 4; ni++) {
            int c = wn + ni * 8 + g;
            fbb[ni][0] = *(const unsigned*)&Bb[c][2 * t];
            fbb[ni][1] = *(const unsigned*)&Bb[c][2 * t + 8];
            fbl[ni][0] = *(const unsigned*)&Bl[c][2 * t];
            fbl[ni][1] = *(const unsigned*)&Bl[c][2 * t + 8];
        }
#pragma unroll
        for (int mi = 0; mi < 4; mi++)
#pragma unroll
            for (int ni = 0; ni < 4; ni++) {
                mma_bf16(acc[mi][ni], fab[mi], fbb[ni]);   // hi*hi
                mma_bf16(acc[mi][ni], fab[mi], fbl[ni]);   // hi*lo
                mma_bf16(acc[mi][ni], fal[mi], fbb[ni]);   // lo*hi
            }
        __syncthreads();
    }

#pragma unroll
    for (int mi = 0; mi < 4; mi++) {
        int r = row0 + wm + mi * 16 + g;
#pragma unroll
        for (int ni = 0; ni < 4; ni++) {
            int c = col0 + wn + ni * 8 + 2 * t;
            if (r < NN)     *(float2*)(C + (size_t)r * DD + c)       = make_float2(acc[mi][ni][0], acc[mi][ni][1]);
            if (r + 8 < NN) *(float2*)(C + (size_t)(r + 8) * DD + c) = make_float2(acc[mi][ni][2], acc[mi][ni][3]);
        }
    }
}

// ================= semantic GEMM (bf16 pre-split A from gather) =================
__global__ __launch_bounds__(256) void sem_mma(const float* __restrict__ b1,
                                               const float* __restrict__ w2) {
    __shared__ __nv_bfloat16 Ab[128][SPAD], Al[128][SPAD];
    __shared__ __nv_bfloat16 Bb[128][SPAD], Bl[128][SPAD];
    __shared__ float sred[128];
    __shared__ float spath[MP];

    int tid = threadIdx.x;
    int row0 = blockIdx.x * 128;

    if (tid < 128) sred[tid] = 0.0f;
    if (tid < MP) spath[tid] = 0.0f;

    int wid = tid >> 5, lane = tid & 31;
    int g = lane >> 2, t = lane & 3;
    int wm = (wid >> 2) * 64, wn = (wid & 3) * 32;

    int arow = tid >> 1;
    int ahalf = tid & 1;

    float acc[4][4][4];
#pragma unroll
    for (int i = 0; i < 4; i++)
#pragma unroll
        for (int j = 0; j < 4; j++)
#pragma unroll
            for (int q = 0; q < 4; q++) acc[i][j][q] = 0.0f;

    const uint4 z4 = make_uint4(0u,0u,0u,0u);
    uint4 a_hi, a_lo, b_hi, b_lo;
    {
        int r = row0 + arow;
        size_t aoff = (size_t)r * DD + ahalf * 8;
        a_hi = (r < RROWS) ? *(const uint4*)(g_zb + aoff) : z4;
        a_lo = (r < RROWS) ? *(const uint4*)(g_zl + aoff) : z4;
        size_t boff = (size_t)arow * DD + ahalf * 8;    // w1t rows 0..127 = HID
        b_hi = *(const uint4*)(g_w1t_hi + boff);
        b_lo = *(const uint4*)(g_w1t_lo + boff);
    }

    const int NK = DD / 16;  // 32
    for (int kt = 0; kt < NK; kt++) {
        *(uint4*)&Ab[arow][ahalf * 8] = a_hi;
        *(uint4*)&Al[arow][ahalf * 8] = a_lo;
        *(uint4*)&Bb[arow][ahalf * 8] = b_hi;
        *(uint4*)&Bl[arow][ahalf * 8] = b_lo;
        __syncthreads();

        if (kt + 1 < NK) {
            int k0 = (kt + 1) * 16;
            int r = row0 + arow;
            size_t aoff = (size_t)r * DD + k0 + ahalf * 8;
            a_hi = (r < RROWS) ? *(const uint4*)(g_zb + aoff) : z4;
            a_lo = (r < RROWS) ? *(const uint4*)(g_zl + aoff) : z4;
            size_t boff = (size_t)arow * DD + k0 + ahalf * 8;
            b_hi = *(const uint4*)(g_w1t_hi + boff);
            b_lo = *(const uint4*)(g_w1t_lo + boff);
        }

        unsigned fab[4][4], fal[4][4];
#pragma unroll
        for (int mi = 0; mi < 4; mi++) {
            int r = wm + mi * 16 + g;
            fab[mi][0] = *(const unsigned*)&Ab[r][2 * t];
            fab[mi][1] = *(const unsigned*)&Ab[r + 8][2 * t];
            fab[mi][2] = *(const unsigned*)&Ab[r][2 * t + 8];
            fab[mi][3] = *(const unsigned*)&Ab[r + 8][2 * t + 8];
            fal[mi][0] = *(const unsigned*)&Al[r][2 * t];
            fal[mi][1] = *(const unsigned*)&Al[r + 8][2 * t];
            fal[mi][2] = *(const unsigned*)&Al[r][2 * t + 8];
            fal[mi][3] = *(const unsigned*)&Al[r + 8][2 * t + 8];
        }
        unsigned fbb[4][2], fbl[4][2];
#pragma unroll
        for (int ni = 0; ni < 4; ni++) {
            int c = wn + ni * 8 + g;
            fbb[ni][0] = *(const unsigned*)&Bb[c][2 * t];
            fbb[ni][1] = *(const unsigned*)&Bb[c][2 * t + 8];
            fbl[ni][0] = *(const unsigned*)&Bl[c][2 * t];
            fbl[ni][1] = *(const unsigned*)&Bl[c][2 * t + 8];
        }
#pragma unroll
        for (int mi = 0; mi < 4; mi++)
#pragma unroll
            for (int ni = 0; ni < 4; ni++) {
                mma_bf16(acc[mi][ni], fab[mi], fbb[ni]);
                mma_bf16(acc[mi][ni], fab[mi], fbl[ni]);
                mma_bf16(acc[mi][ni], fal[mi], fbb[ni]);
            }
        __syncthreads();
    }

    // epilogue: per-row sum of tanh(c + b1) * w2, accumulate into per-path sums
#pragma unroll
    for (int mi = 0; mi < 4; mi++) {
        float s0 = 0.f, s1 = 0.f;
#pragma unroll
        for (int ni = 0; ni < 4; ni++) {
            int c = wn + ni * 8 + 2 * t;
            float w2a = w2[c], w2b = w2[c + 1];
            float b1a = b1[c], b1b = b1[c + 1];
            s0 += tanhf(acc[mi][ni][0] + b1a) * w2a + tanhf(acc[mi][ni][1] + b1b) * w2b;
            s1 += tanhf(acc[mi][ni][2] + b1a) * w2a + tanhf(acc[mi][ni][3] + b1b) * w2b;
        }
        s0 += __shfl_xor_sync(0xffffffffu, s0, 1);
        s0 += __shfl_xor_sync(0xffffffffu, s0, 2);
        s1 += __shfl_xor_sync(0xffffffffu, s1, 1);
        s1 += __shfl_xor_sync(0xffffffffu, s1, 2);
        if (t == 0) {
            atomicAdd(&sred[wm + mi * 16 + g], s0);
            atomicAdd(&sred[wm + mi * 16 + g + 8], s1);
        }
    }
    __syncthreads();
    if (tid < 128) {
        int gr = row0 + tid;
        if (gr < RROWS) atomicAdd(&spath[gr % MP], sred[tid]);
    }
    __syncthreads();
    if (tid < MP) atomicAdd(&g_wsum[tid], spath[tid]);
}

// ---------------- el/er ----------------
__global__ void el_er_kernel(const float* __restrict__ attn_l, const float* __restrict__ attn_r) {
    int gw = blockIdx.x * 8 + (threadIdx.x >> 5);
    if (gw >= MP * NN) return;
    int m = gw / NN, n = gw % NN;
    int lane = threadIdx.x & 31;
    const float* frow = g_feat + ((size_t)m * NN + n) * DD;

    float pl[8], pr[8];
#pragma unroll
    for (int h = 0; h < 8; h++) { pl[h] = 0.f; pr[h] = 0.f; }
#pragma unroll
    for (int j = 0; j < 16; j++) {
        int c = lane + 32 * j;
        int hh = j >> 1;
        int fi = lane + 32 * (j & 1);
        float f = frow[c];
        pl[hh] += f * attn_l[(m * NH + hh) * FH + fi];
        pr[hh] += f * attn_r[(m * NH + hh) * FH + fi];
    }
#pragma unroll
    for (int off = 16; off > 0; off >>= 1) {
#pragma unroll
        for (int h = 0; h < 8; h++) {
            pl[h] += __shfl_xor_sync(0xffffffffu, pl[h], off);
            pr[h] += __shfl_xor_sync(0xffffffffu, pr[h], off);
        }
    }
    if (lane < 8) {
        g_el[((size_t)m * NN + n) * NH + lane] = pl[lane];
        g_er[((size_t)m * NN + n) * NH + lane] = pr[lane];
    }
}

// ---------------- CSR build ----------------
__global__ void hist_kernel(const int* __restrict__ dst) {
    int i = blockIdx.x * 256 + threadIdx.x;
    if (i >= MP * NE) return;
    int m = i / NE;
    atomicAdd(&g_cnt[m][dst[i]], 1);
}

__global__ void scanA_kernel() {
    int m = blockIdx.y;
    int c0 = blockIdx.x * 1024;
    int tid = threadIdx.x;
    __shared__ int s[256];
    int v[4]; int sum = 0;
#pragma unroll
    for (int t = 0; t < 4; t++) {
        int i = c0 + tid * 4 + t;
        v[t] = (i < NN) ? g_cnt[m][i] : 0;
        sum += v[t];
    }
    s[tid] = sum;
    __syncthreads();
    for (int off = 1; off < 256; off <<= 1) {
        int t = (tid >= off) ? s[tid - off] : 0;
        __syncthreads();
        s[tid] += t;
        __syncthreads();
    }
    int run = s[tid] - sum;
#pragma unroll
    for (int t = 0; t < 4; t++) {
        int i = c0 + tid * 4 + t;
        if (i < NN) g_rowptr[m][i] = run;
        run += v[t];
    }
    if (tid == 255) g_part[m][blockIdx.x] = s[255];
}

__global__ void scanB_kernel() {
    int m = blockIdx.x;
    if (threadIdx.x == 0) {
        int run = 0;
        const int nchunk = (NN + 1023) / 1024;
        for (int c = 0; c < nchunk; c++) { int t = g_part[m][c]; g_part[m][c] = run; run += t; }
    }
}

__global__ void scanC_kernel() {
    int m = blockIdx.y;
    int i = blockIdx.x * 256 + threadIdx.x;
    if (i < NN) {
        g_rowptr[m][i] += g_part[m][i >> 10];
        g_cnt[m][i] = 0;
    }
    if (i == 0) g_rowptr[m][NN] = NE;
}

__global__ void scatter_kernel(const int* __restrict__ dst) {
    int i = blockIdx.x * 256 + threadIdx.x;
    if (i >= MP * NE) return;
    int m = i / NE, e = i % NE;
    int d = dst[i];
    int pos = g_rowptr[m][d] + atomicAdd(&g_cnt[m][d], 1);
    g_colidx[m][pos] = e;
}

// ---------------- gather: per-dst softmax + aggregation; writes z as bf16 hi/lo ----------------
__global__ __launch_bounds__(256) void gather_kernel(const int* __restrict__ src,
                                                     const float* __restrict__ bias,
                                                     float* __restrict__ out_alpha) {
    int m = blockIdx.y;
    int n = blockIdx.x * 8 + (threadIdx.x >> 5);
    if (n >= NN) return;
    int lane = threadIdx.x & 31;

    int beg = g_rowptr[m][n];
    int end = g_rowptr[m][n + 1];

    const float* el = g_el + (size_t)m * NN * NH;
    float er8[8];
    {
        const float4* e4 = (const float4*)(g_er + ((size_t)m * NN + n) * NH);
        float4 a = e4[0], b = e4[1];
        er8[0] = a.x; er8[1] = a.y; er8[2] = a.z; er8[3] = a.w;
        er8[4] = b.x; er8[5] = b.y; er8[6] = b.z; er8[7] = b.w;
    }

    float4 acc[4];
#pragma unroll
    for (int j = 0; j < 4; j++) acc[j] = make_float4(0.f, 0.f, 0.f, 0.f);

    if (end > beg) {
        float mx[8];
#pragma unroll
        for (int h = 0; h < 8; h++) mx[h] = -INFINITY;
        for (int idx = beg + lane; idx < end; idx += 32) {
            int e = g_colidx[m][idx];
            int s = src[(size_t)m * NE + e];
            const float4* s4 = (const float4*)(el + (size_t)s * NH);
            float4 a = s4[0], b = s4[1];
            float ev[8] = {a.x, a.y, a.z, a.w, b.x, b.y, b.z, b.w};
#pragma unroll
            for (int h = 0; h < 8; h++) {
                float x = ev[h] + er8[h];
                x = (x > 0.f) ? x : NEG_SLOPE * x;
                mx[h] = fmaxf(mx[h], x);
            }
        }
#pragma unroll
        for (int off = 16; off > 0; off >>= 1)
#pragma unroll
            for (int h = 0; h < 8; h++) mx[h] = fmaxf(mx[h], __shfl_xor_sync(0xffffffffu, mx[h], off));

        float sm[8];
#pragma unroll
        for (int h = 0; h < 8; h++) sm[h] = 0.f;
        for (int idx = beg + lane; idx < end; idx += 32) {
            int e = g_colidx[m][idx];
            int s = src[(size_t)m * NE + e];
            const float4* s4 = (const float4*)(el + (size_t)s * NH);
            float4 a = s4[0], b = s4[1];
            float ev[8] = {a.x, a.y, a.z, a.w, b.x, b.y, b.z, b.w};
#pragma unroll
            for (int h = 0; h < 8; h++) {
                float x = ev[h] + er8[h];
                x = (x > 0.f) ? x : NEG_SLOPE * x;
                sm[h] += expf(x - mx[h]);
            }
        }
#pragma unroll
        for (int off = 16; off > 0; off >>= 1)
#pragma unroll
            for (int h = 0; h < 8; h++) sm[h] += __shfl_xor_sync(0xffffffffu, sm[h], off);

        float inv[8];
#pragma unroll
        for (int h = 0; h < 8; h++) inv[h] = 1.0f / (sm[h] + 1e-9f);

        int hsel = lane & 7;
        for (int idx = beg; idx < end; idx++) {
            int e = g_colidx[m][idx];
            int s = src[(size_t)m * NE + e];
            float x = el[(size_t)s * NH + hsel] + er8[hsel];
            x = (x > 0.f) ? x : NEG_SLOPE * x;
            float a_h = expf(x - mx[hsel]) * inv[hsel];
            if (lane < 8) out_alpha[((size_t)m * NE + e) * NH + lane] = a_h;
            const float4* f4 = (const float4*)(g_feat + ((size_t)m * NN + s) * DD);
#pragma unroll
            for (int j = 0; j < 4; j++) {
                int hh = 2 * j + (lane >> 4);
                float a = __shfl_sync(0xffffffffu, a_h, hh);
                float4 f = f4[lane + 32 * j];
                acc[j].x += a * f.x; acc[j].y += a * f.y;
                acc[j].z += a * f.z; acc[j].w += a * f.w;
            }
        }
    }

    // epilogue: elu(acc + bias) -> z split into bf16 hi/lo
    const float4* b4 = (const float4*)(bias + (size_t)m * DD);
    size_t zoff = ((size_t)n * MP + m) * DD;
#pragma unroll
    for (int j = 0; j < 4; j++) {
        float4 v = acc[j];
        float4 bb = b4[lane + 32 * j];
        v.x += bb.x; v.y += bb.y; v.z += bb.z; v.w += bb.w;
        v.x = (v.x > 0.f) ? v.x : expm1f(v.x);
        v.y = (v.y > 0.f) ? v.y : expm1f(v.y);
        v.z = (v.z > 0.f) ? v.z : expm1f(v.z);
        v.w = (v.w > 0.f) ? v.w : expm1f(v.w);
        __nv_bfloat16 h0,h1,h2,h3,l0,l1,l2,l3;
        split2(v.x,h0,l0); split2(v.y,h1,l1); split2(v.z,h2,l2); split2(v.w,h3,l3);
        size_t eo = zoff + 4 * lane + 128 * j;
        *(uint2*)(g_zb + eo) = make_uint2(pack2(h0,h1), pack2(h2,h3));
        *(uint2*)(g_zl + eo) = make_uint2(pack2(l0,l1), pack2(l2,l3));
    }
}

// ---------------- beta ----------------
__global__ void beta_kernel(float* __restrict__ out_beta) {
    if (threadIdx.x == 0 && blockIdx.x == 0) {
        float w[MP];
        float mx = -INFINITY;
        for (int m = 0; m < MP; m++) { w[m] = g_wsum[m] / (float)NN; mx = fmaxf(mx, w[m]); }
        float s = 0.f;
        for (int m = 0; m < MP; m++) { w[m] = expf(w[m] - mx); s += w[m]; }
        for (int m = 0; m < MP; m++) {
            float b = w[m] / s;
            g_beta[m] = b;
            out_beta[m] = b;
        }
    }
}

// ---------------- combine: gat_out = sum_m beta[m] * (zb+zl) ----------------
__global__ void combine_kernel(float* __restrict__ out) {
    int i = blockIdx.x * 256 + threadIdx.x;   // group of 4 elements over NN*128 groups
    if (i >= NN * 128) return;
    int n = i >> 7, c = i & 127;
    float b[MP] = {g_beta[0], g_beta[1], g_beta[2]};
    float r0 = 0.f, r1 = 0.f, r2 = 0.f, r3 = 0.f;
#pragma unroll
    for (int m = 0; m < MP; m++) {
        size_t eo = ((size_t)n * MP + m) * DD + 4 * c;
        uint2 hb = *(const uint2*)(g_zb + eo);
        uint2 lb = *(const uint2*)(g_zl + eo);
        float v0 = __bfloat162float(__ushort_as_bfloat16((unsigned short)(hb.x & 0xffff)))
                 + __bfloat162float(__ushort_as_bfloat16((unsigned short)(lb.x & 0xffff)));
        float v1 = __bfloat162float(__ushort_as_bfloat16((unsigned short)(hb.x >> 16)))
                 + __bfloat162float(__ushort_as_bfloat16((unsigned short)(lb.x >> 16)));
        float v2 = __bfloat162float(__ushort_as_bfloat16((unsigned short)(hb.y & 0xffff)))
                 + __bfloat162float(__ushort_as_bfloat16((unsigned short)(lb.y & 0xffff)));
        float v3 = __bfloat162float(__ushort_as_bfloat16((unsigned short)(hb.y >> 16)))
                 + __bfloat162float(__ushort_as_bfloat16((unsigned short)(lb.y >> 16)));
        r0 += b[m] * v0; r1 += b[m] * v1; r2 += b[m] * v2; r3 += b[m] * v3;
    }
    ((float4*)out)[i] = make_float4(r0, r1, r2, r3);
}

// ---------------- launch ----------------
extern "C" void kernel_launch(void* const* d_in, const int* in_sizes, int n_in,
                              void* d_out, int out_size) {
    const float* h      = (const float*)d_in[0];
    const float* W      = (const float*)d_in[1];
    const float* attn_l = (const float*)d_in[2];
    const float* attn_r = (const float*)d_in[3];
    const float* bias   = (const float*)d_in[4];
    const float* sem_w1 = (const float*)d_in[5];
    const float* sem_b1 = (const float*)d_in[6];
    const float* sem_w2 = (const float*)d_in[7];
    const int*   src    = (const int*)d_in[8];
    const int*   dst    = (const int*)d_in[9];

    float* out       = (float*)d_out;
    float* out_alpha = out + (size_t)NN * DD;
    float* out_beta  = out_alpha + (size_t)MP * NE * NH;

    init_kernel<<<(MP * NN + 255) / 256, 256>>>();

    // pre-split inputs to bf16 hi/lo (W, w1 transposed)
    split_h_kernel<<<(NN * INS / 4 + 255) / 256, 256>>>(h);
    split_W_kernel<<<(MP * INS * DD + 255) / 256, 256>>>(W);
    split_w1_kernel<<<(DD * HID + 255) / 256, 256>>>(sem_w1);

    {
        dim3 g(DD / 128, MB1, MP);
        gemm_feat_mma<<<g, 256>>>(0);
    }

    el_er_kernel<<<(MP * NN + 7) / 8, 256>>>(attn_l, attn_r);

    hist_kernel<<<(MP * NE + 255) / 256, 256>>>(dst);
    {
        dim3 g((NN + 1023) / 1024, MP);
        scanA_kernel<<<g, 256>>>();
    }
    scanB_kernel<<<MP, 32>>>();
    {
        dim3 g((NN + 255) / 256, MP);
        scanC_kernel<<<g, 256>>>();
    }
    scatter_kernel<<<(MP * NE + 255) / 256, 256>>>(dst);

    {
        dim3 g((NN + 7) / 8, MP);
        gather_kernel<<<g, 256>>>(src, bias, out_alpha);
    }

    sem_mma<<<(RROWS + 127) / 128, 256>>>(sem_b1, sem_w2);
    beta_kernel<<<1, 32>>>(out_beta);
    combine_kernel<<<(NN * 128 + 255) / 256, 256>>>(out);
}